// round 17
// baseline (speedup 1.0000x reference)
#include <cuda_runtime.h>
#include <cuda_bf16.h>
#include <cuda_fp16.h>
#include <math.h>
#include <stdint.h>

// Problem constants
#define T_STEPS 512
#define B_SZ    64
#define F_SZ    128
#define H_SZ    512
#define O_SZ    16
#define G_SZ    (3 * H_SZ)   // 1536

#define NCTA2   128
#define NTHR2   256
#define JPC     8
#define GRPCTA  64
#define NGRP    2

#define BSM_U32     (3 * 32 * 32 * 2)
#define DST         26
#define DSM_FLOATS  (8 * 16 * DST)
#define SMEM2_BYTES (BSM_U32 * 4 + DSM_FLOATS * 4)

#define NTILES_A    2048
#define NTILES_WN   192

__device__ float g_XG[T_STEPS * B_SZ * G_SZ];
__device__ float g_HS[T_STEPS * B_SZ * H_SZ];
__device__ uint32_t g_Hfrag[2][4 * 32 * 128];
__device__ uint4 g_XF[NTILES_A * 8 * 32];
__device__ uint2 g_WF[NTILES_WN * 8 * 32];
__device__ __align__(128) unsigned g_flagsB[NGRP][2][GRPCTA][32];
__device__ __align__(128) unsigned g_cntB[NGRP][2][32];

__device__ __forceinline__ float fsig(float x) { return 1.0f / (1.0f + __expf(-x)); }
__device__ __forceinline__ float ftanh(float x) { return 2.0f / (1.0f + __expf(-2.0f * x)) - 1.0f; }

__device__ __forceinline__ uint32_t pkhf(float a, float b) {
    __half2 h = __floats2half2_rn(a, b);
    return *(uint32_t*)&h;
}

__device__ __forceinline__ void hmma16(float* d, const uint4& a, uint32_t b0, uint32_t b1) {
    asm volatile(
        "mma.sync.aligned.m16n8k16.row.col.f32.f16.f16.f32 "
        "{%0,%1,%2,%3}, {%4,%5,%6,%7}, {%8,%9}, {%0,%1,%2,%3};"
        : "+f"(d[0]), "+f"(d[1]), "+f"(d[2]), "+f"(d[3])
        : "r"(a.x), "r"(a.y), "r"(a.z), "r"(a.w), "r"(b0), "r"(b1));
}

__global__ void __launch_bounds__(256, 4)
k0_pack(const float* __restrict__ x, const float* __restrict__ wih)
{
    const int tid  = threadIdx.x;
    const int ks   = tid >> 5;
    const int lane = tid & 31;
    const int cb   = blockIdx.x;

    if (cb < NTILES_A) {
        const int row0 = cb * 16 + (lane >> 2);
        const int kc   = ks * 16 + (lane & 3) * 2;
        const float* r0 = &x[row0 * F_SZ + kc];
        const float* r1 = r0 + 8 * F_SZ;
        float2 x00 = *(const float2*)r0;
        float2 x10 = *(const float2*)r1;
        float2 x01 = *(const float2*)(r0 + 8);
        float2 x11 = *(const float2*)(r1 + 8);
        g_XF[(cb * 8 + ks) * 32 + lane] =
            make_uint4(pkhf(x00.x, x00.y), pkhf(x10.x, x10.y),
                       pkhf(x01.x, x01.y), pkhf(x11.x, x11.y));
    } else {
        const int ntg = cb - NTILES_A;
        const int n   = ntg * 8 + (lane >> 2);
        const int kc  = ks * 16 + (lane & 3) * 2;
        const float* wr = &wih[n * F_SZ + kc];
        g_WF[(ntg * 8 + ks) * 32 + lane] =
            make_uint2(pkhf(wr[0], wr[1]), pkhf(wr[8], wr[9]));
    }
}

__global__ void __launch_bounds__(256, 4)
k1_xg(const float* __restrict__ bih)
{
    const int tid  = threadIdx.x;
    const int wid  = tid >> 5;
    const int lane = tid & 31;
    const int tile = blockIdx.y * 8 + wid;
    const int n0   = blockIdx.x * 64;
    const int ntb  = blockIdx.x * 8;

    float acc[8][4];
#pragma unroll
    for (int nt = 0; nt < 8; nt++)
#pragma unroll
        for (int i = 0; i < 4; i++) acc[nt][i] = 0.f;

#pragma unroll
    for (int ks = 0; ks < 8; ks++) {
        uint4 ah = __ldg(&g_XF[(tile * 8 + ks) * 32 + lane]);
#pragma unroll
        for (int nt = 0; nt < 8; nt++) {
            uint2 bw = __ldg(&g_WF[((ntb + nt) * 8 + ks) * 32 + lane]);
            hmma16(acc[nt], ah, bw.x, bw.y);
        }
    }

    const int gid = lane >> 2;
    const int tig = lane & 3;
    const int row0 = tile * 16 + gid;
#pragma unroll
    for (int nt = 0; nt < 8; nt++) {
        int col = n0 + nt * 8 + tig * 2;
        float2 bb = *(const float2*)&bih[col];
        *(float2*)&g_XG[row0 * G_SZ + col] =
            make_float2(acc[nt][0] + bb.x, acc[nt][1] + bb.y);
        *(float2*)&g_XG[(row0 + 8) * G_SZ + col] =
            make_float2(acc[nt][2] + bb.x, acc[nt][3] + bb.y);
    }
}

__global__ void __launch_bounds__(NTHR2, 1)
k2_gru(const float* __restrict__ wHH, const float* __restrict__ bHH)
{
    extern __shared__ uint32_t sm[];
    uint32_t* Bsm = sm;
    float*    Dsm = (float*)(sm + BSM_U32);

    const int tid  = threadIdx.x;
    const int wid  = tid >> 5;
    const int lane = tid & 31;
    const int bid  = blockIdx.x;
    const int grp  = bid & 1;
    const int b0   = grp * 32;
    const int jblk = bid >> 1;
    const int j0   = jblk * JPC;

    for (int idx = tid; idx < 3 * 32 * 32; idx += NTHR2) {
        int el = idx & 31;
        int ks = (idx >> 5) & 31;
        int nt = (idx >> 10) % 3;
        int n  = nt * 8 + (el >> 2);
        int jl = n / 3, g = n % 3;
        const float* wr = &wHH[(g * H_SZ + j0 + jl) * H_SZ + ks * 16 + (el & 3) * 2];
        int base = ((nt * 32 + ks) * 32 + el) * 2;
        Bsm[base    ] = pkhf(wr[0], wr[1]);
        Bsm[base + 1] = pkhf(wr[8], wr[9]);
    }

    const int half = tid >> 7;
    const int eb   = tid >> 3;
    const int jl   = tid & 7;
    const float bR = __ldg(&bHH[0 * H_SZ + j0 + jl]);
    const float bZ = __ldg(&bHH[1 * H_SZ + j0 + jl]);
    const float bN = __ldg(&bHH[2 * H_SZ + j0 + jl]);
    float hprev = 0.f;
    __syncthreads();

    const int whalf = wid >> 2;
    const int kh    = wid & 3;
    const int mtg   = grp * 2 + whalf;
    const int ks0   = kh * 8;
    const int gid   = lane >> 2;
    const int tig   = lane & 3;

    const unsigned* myflag = &g_flagsB[grp][whalf][kh * 16 + (lane & 15)][0];
    unsigned* ownflag = &g_flagsB[grp][half][jblk][0];

    for (int t = 0; t < T_STEPS; t++) {
        const int gbase = (t * B_SZ + b0 + eb) * G_SZ + j0 + jl;
        float xr = __ldg(&g_XG[gbase]);
        float xz = __ldg(&g_XG[gbase + H_SZ]);
        float xn = __ldg(&g_XG[gbase + 2 * H_SZ]);

        if (t > 0) {
            // MLP-4 relaxed poll + final acquire (detect granularity /4)
            if (lane < 16) {
                unsigned v;
                do {
                    unsigned a0, a1, a2, a3;
                    asm volatile(
                        "ld.relaxed.gpu.u32 %0, [%4];\n\t"
                        "ld.relaxed.gpu.u32 %1, [%4];\n\t"
                        "ld.relaxed.gpu.u32 %2, [%4];\n\t"
                        "ld.relaxed.gpu.u32 %3, [%4];"
                        : "=r"(a0), "=r"(a1), "=r"(a2), "=r"(a3)
                        : "l"(myflag) : "memory");
                    v = max(max(a0, a1), max(a2, a3));
                } while (v < (unsigned)t);
                asm volatile("ld.acquire.gpu.u32 %0, [%1];"
                             : "=r"(v) : "l"(myflag) : "memory");
            }
            __syncwarp();

            const uint32_t* hfr =
                &g_Hfrag[(t + 1) & 1][(mtg * 32 + ks0) * 128 + lane * 4];

            uint4 ah[8];
#pragma unroll
            for (int kk = 0; kk < 8; kk++)
                ah[kk] = __ldcg((const uint4*)&hfr[kk * 128]);

            float acc[3][4];
#pragma unroll
            for (int nt = 0; nt < 3; nt++)
#pragma unroll
                for (int i = 0; i < 4; i++) acc[nt][i] = 0.f;

#pragma unroll
            for (int kk = 0; kk < 8; kk++) {
                int ks = ks0 + kk;
#pragma unroll
                for (int nt = 0; nt < 3; nt++) {
                    uint2 bw = *(const uint2*)&Bsm[((nt * 32 + ks) * 32 + lane) * 2];
                    hmma16(acc[nt], ah[kk], bw.x, bw.y);
                }
            }

            const int slot = whalf * 4 + kh;
#pragma unroll
            for (int nt = 0; nt < 3; nt++) {
                int col = nt * 8 + tig * 2;
                *(float2*)&Dsm[(slot * 16 + gid) * DST + col] =
                    make_float2(acc[nt][0], acc[nt][1]);
                *(float2*)&Dsm[(slot * 16 + gid + 8) * DST + col] =
                    make_float2(acc[nt][2], acc[nt][3]);
            }
            if (whalf == 0) asm volatile("bar.sync 1, 128;" ::: "memory");
            else            asm volatile("bar.sync 2, 128;" ::: "memory");
        }

        float s0 = 0.f, s1 = 0.f, s2 = 0.f;
        if (t > 0) {
            const int rr = eb & 15;
#pragma unroll
            for (int kq = 0; kq < 4; kq++) {
                const float* pr = &Dsm[((half * 4 + kq) * 16 + rr) * DST + jl * 3];
                s0 += pr[0]; s1 += pr[1]; s2 += pr[2];
            }
        }

        float rg = fsig(xr + s0 + bR);
        float zg = fsig(xz + s1 + bZ);
        float ng = ftanh(xn + rg * (s2 + bN));
        float hnew = (1.0f - zg) * ng + zg * hprev;
        hprev = hnew;

        float hn1 = __shfl_down_sync(0xffffffffu, hnew, 1);
        if (!(jl & 1)) {
            uint32_t* hw = g_Hfrag[t & 1];
            int r   = b0 + eb;
            int c   = j0 + jl;
            int ks  = c >> 4;
            int lnw = (r & 7) * 4 + ((c >> 1) & 3);
            int reg = (((c >> 3) & 1) << 1) | ((r >> 3) & 1);
            hw[((r >> 4) * 32 + ks) * 128 + lnw * 4 + reg] = pkhf(hnew, hn1);
        }

        if (half == 0) asm volatile("bar.sync 1, 128;" ::: "memory");
        else           asm volatile("bar.sync 2, 128;" ::: "memory");
        if ((tid & 127) == 0)
            asm volatile("st.release.gpu.u32 [%0], %1;"
                         :: "l"(ownflag), "r"((unsigned)(t + 1)) : "memory");

        g_HS[(t * B_SZ + b0 + eb) * H_SZ + j0 + jl] = hnew;
    }

    if ((tid & 127) == 0) {
        int h = tid >> 7;
        if (atomicAdd(&g_cntB[grp][h][0], 1u) == (unsigned)(GRPCTA - 1)) {
            atomicExch(&g_cntB[grp][h][0], 0u);
            for (int i = 0; i < GRPCTA; i++)
                g_flagsB[grp][h][i][0] = 0u;
            __threadfence();
        }
    }
}

__global__ void __launch_bounds__(128, 4)
k3_out(const float* __restrict__ wout, const float* __restrict__ bout,
       float* __restrict__ y)
{
    __shared__ float As[32][132];
    __shared__ float Wsh[32][16];

    const int tid = threadIdx.x;
    const int tx = tid & 3;
    const int ty = tid >> 2;
    const int m0 = blockIdx.x * 128;

    float c[4][4];
#pragma unroll
    for (int i = 0; i < 4; i++)
#pragma unroll
        for (int jj = 0; jj < 4; jj++) c[i][jj] = 0.f;

    for (int kc = 0; kc < H_SZ; kc += 32) {
        __syncthreads();
#pragma unroll
        for (int i = 0; i < 8; i++) {
            int lin = tid + i * 128;
            int m = lin >> 3, k4 = lin & 7;
            float4 v = *(const float4*)&g_HS[(m0 + m) * H_SZ + kc + k4 * 4];
            As[k4 * 4 + 0][m] = v.x; As[k4 * 4 + 1][m] = v.y;
            As[k4 * 4 + 2][m] = v.z; As[k4 * 4 + 3][m] = v.w;
        }
#pragma unroll
        for (int i = 0; i < 4; i++) {
            int lin = tid + i * 128;
            int n = lin >> 5, k = lin & 31;
            Wsh[k][n] = wout[n * H_SZ + kc + k];
        }
        __syncthreads();
#pragma unroll
        for (int k = 0; k < 32; k++) {
            float a[4], w[4];
#pragma unroll
            for (int i = 0; i < 4; i++) a[i] = As[k][ty * 4 + i];
#pragma unroll
            for (int jj = 0; jj < 4; jj++) w[jj] = Wsh[k][tx * 4 + jj];
#pragma unroll
            for (int i = 0; i < 4; i++)
#pragma unroll
                for (int jj = 0; jj < 4; jj++)
                    c[i][jj] = fmaf(a[i], w[jj], c[i][jj]);
        }
    }

    float bb[4];
#pragma unroll
    for (int jj = 0; jj < 4; jj++) bb[jj] = __ldg(&bout[tx * 4 + jj]);
#pragma unroll
    for (int i = 0; i < 4; i++) {
        float4 v;
        v.x = c[i][0] + bb[0]; v.y = c[i][1] + bb[1];
        v.z = c[i][2] + bb[2]; v.w = c[i][3] + bb[3];
        *(float4*)&y[(m0 + ty * 4 + i) * O_SZ + tx * 4] = v;
    }
}

extern "C" void kernel_launch(void* const* d_in, const int* in_sizes, int n_in,
                              void* d_out, int out_size)
{
    const float* x    = (const float*)d_in[0];
    const float* wih  = (const float*)d_in[1];
    const float* whh  = (const float*)d_in[2];
    const float* bih  = (const float*)d_in[3];
    const float* bhh  = (const float*)d_in[4];
    const float* wout = (const float*)d_in[5];
    const float* bout = (const float*)d_in[6];
    float* y = (float*)d_out;

    cudaFuncSetAttribute(k2_gru, cudaFuncAttributeMaxDynamicSharedMemorySize,
                         SMEM2_BYTES);

    k0_pack<<<NTILES_A + NTILES_WN, 256>>>(x, wih);
    k1_xg<<<dim3(G_SZ / 64, NTILES_A / 8), 256>>>(bih);
    k2_gru<<<NCTA2, NTHR2, SMEM2_BYTES>>>(whh, bhh);
    k3_out<<<(T_STEPS * B_SZ) / 128, 128>>>(wout, bout, y);
}